// round 17
// baseline (speedup 1.0000x reference)
#include <cuda_runtime.h>
#include <math.h>

// Fixed problem shape (B, N, M) = (64, 2048, 256)
#define BB 64
#define NN 2048
#define MM 256
#define EPS_COS 1e-16f
#define EPS_NRM 1e-8f
#define NSPLIT 16            // blocks per b
#define CHUNK (NN / NSPLIT)  // 128 rows per block (8 warps x 16 rows)

// Static scratch (allocation-free rule). Zero-initialized at module load.
__device__ float g_psum[BB * NSPLIT];
__device__ float g_pc[BB * NSPLIT];
__device__ float g_pacc[BB * NSPLIT * MM];
__device__ unsigned int g_cnt[BB];

// ===================================================================
// Single-pass fused kernel, max-free softmax, 4-row batched reductions.
// Phase 1: 4 rows' lane-partial dot/ss (v discarded).
// Phase 2: 8 independent shuffle-reduce chains + 4 independent exp chains.
// Phase 3: re-load the 4 rows (L1 hits, volatile to defeat CSE), a += f*v.
// grid = (BB, NSPLIT), block = 256 (8 warps).
// Last block of each b merges the 16 partials and writes out.
// ===================================================================
__global__ void __launch_bounds__(256)
fused_kernel(const float4* __restrict__ mem4,
             const float4* __restrict__ k4,
             const float*  __restrict__ kf,
             const float*  __restrict__ g,
             const float*  __restrict__ w_prev,
             const int*    __restrict__ w_lu_prev,
             float* __restrict__ out) {
    int b     = blockIdx.x;
    int split = blockIdx.y;
    int t     = threadIdx.x;
    int warp  = t >> 5;
    int lane  = t & 31;

    __shared__ float4 sacc4[8][64];     // 8 KB: per-warp accumulators
    __shared__ float  ssum[8], scp[8], red2[2];
    __shared__ unsigned int s_old;

    // per-lane k slice (with eps) in registers: k[b, lane*8 .. lane*8+7]
    float4 ka = k4[b * 64 + lane * 2];
    float4 kb = k4[b * 64 + lane * 2 + 1];
    ka.x += EPS_COS; ka.y += EPS_COS; ka.z += EPS_COS; ka.w += EPS_COS;
    kb.x += EPS_COS; kb.y += EPS_COS; kb.z += EPS_COS; kb.w += EPS_COS;

    // inv_knrm (from registers; uniform across warps)
    float ssk = 0.f;
    ssk = fmaf(ka.x, ka.x, ssk); ssk = fmaf(ka.y, ka.y, ssk);
    ssk = fmaf(ka.z, ka.z, ssk); ssk = fmaf(ka.w, ka.w, ssk);
    ssk = fmaf(kb.x, kb.x, ssk); ssk = fmaf(kb.y, kb.y, ssk);
    ssk = fmaf(kb.z, kb.z, ssk); ssk = fmaf(kb.w, kb.w, ssk);
    #pragma unroll
    for (int o = 16; o; o >>= 1) ssk += __shfl_xor_sync(0xffffffffu, ssk, o);
    float inv_knrm = 1.f / fmaxf(sqrtf(ssk), EPS_NRM);

    float gb = g[b];
    int   n0 = split * CHUNK;
    const size_t rowbase = (size_t)b * NN;

    float wsum = 0.f, cpart = 0.f;
    float4 a0 = make_float4(0.f, 0.f, 0.f, 0.f);
    float4 a1 = make_float4(0.f, 0.f, 0.f, 0.f);

    for (int batch = 0; batch < 4; batch++) {
        int itbase = batch * 4;
        float dotj[4], ssj[4];

        // ---- phase 1: lane-partial dot/ss for 4 rows (v discarded) ----
        #pragma unroll
        for (int j = 0; j < 4; j++) {
            int n = n0 + (itbase + j) * 8 + warp;
            const float4* p = mem4 + (rowbase + n) * 64 + lane * 2;
            float4 v0 = p[0];
            float4 v1 = p[1];
            float dot = 0.f, ss = 0.f, me;
            me = v0.x + EPS_COS; dot = fmaf(me, ka.x, dot); ss = fmaf(me, me, ss);
            me = v0.y + EPS_COS; dot = fmaf(me, ka.y, dot); ss = fmaf(me, me, ss);
            me = v0.z + EPS_COS; dot = fmaf(me, ka.z, dot); ss = fmaf(me, me, ss);
            me = v0.w + EPS_COS; dot = fmaf(me, ka.w, dot); ss = fmaf(me, me, ss);
            me = v1.x + EPS_COS; dot = fmaf(me, kb.x, dot); ss = fmaf(me, me, ss);
            me = v1.y + EPS_COS; dot = fmaf(me, kb.y, dot); ss = fmaf(me, me, ss);
            me = v1.z + EPS_COS; dot = fmaf(me, kb.z, dot); ss = fmaf(me, me, ss);
            me = v1.w + EPS_COS; dot = fmaf(me, kb.w, dot); ss = fmaf(me, me, ss);
            dotj[j] = dot;
            ssj[j]  = ss;
        }

        // ---- phase 2a: 8 interleaved butterfly chains ----
        #pragma unroll
        for (int o = 16; o; o >>= 1) {
            #pragma unroll
            for (int j = 0; j < 4; j++) {
                dotj[j] += __shfl_xor_sync(0xffffffffu, dotj[j], o);
                ssj[j]  += __shfl_xor_sync(0xffffffffu, ssj[j],  o);
            }
        }

        // ---- phase 2b: 4 independent score/exp chains ----
        float fj[4];
        #pragma unroll
        for (int j = 0; j < 4; j++) {
            int n = n0 + (itbase + j) * 8 + warp;
            float nrm = fmaxf(sqrtf(ssj[j]), EPS_NRM);
            float s   = __fdividef(dotj[j], nrm) * inv_knrm;
            float ex  = __expf(s);
            float lu  = (float)w_lu_prev[b * NN + n];   // warp-uniform LDG
            float wrp = w_prev[b * 2 * NN + NN + n];    // w_prev[b,1,n]
            float ww  = gb * wrp + (1.f - gb) * lu;
            wsum  += ex;
            cpart += ex * ww;
            fj[j]  = ex * (1.f - lu);
        }

        // ---- phase 3: re-load rows (L1 hits; volatile defeats CSE) ----
        #pragma unroll
        for (int j = 0; j < 4; j++) {
            int n = n0 + (itbase + j) * 8 + warp;
            const float* addr = (const float*)(mem4 + (rowbase + n) * 64 + lane * 2);
            float4 v0, v1;
            asm volatile("ld.global.nc.v4.f32 {%0,%1,%2,%3}, [%4];"
                         : "=f"(v0.x), "=f"(v0.y), "=f"(v0.z), "=f"(v0.w)
                         : "l"(addr));
            asm volatile("ld.global.nc.v4.f32 {%0,%1,%2,%3}, [%4];"
                         : "=f"(v1.x), "=f"(v1.y), "=f"(v1.z), "=f"(v1.w)
                         : "l"(addr + 4));
            float f = fj[j];
            a0.x = fmaf(f, v0.x, a0.x);
            a0.y = fmaf(f, v0.y, a0.y);
            a0.z = fmaf(f, v0.z, a0.z);
            a0.w = fmaf(f, v0.w, a0.w);
            a1.x = fmaf(f, v1.x, a1.x);
            a1.y = fmaf(f, v1.y, a1.y);
            a1.z = fmaf(f, v1.z, a1.z);
            a1.w = fmaf(f, v1.w, a1.w);
        }
    }

    // ---- block merge across 8 warps (plain sums) ----
    sacc4[warp][lane * 2]     = a0;
    sacc4[warp][lane * 2 + 1] = a1;
    if (lane == 0) { ssum[warp] = wsum; scp[warp] = cpart; }
    __syncthreads();

    int idx = b * NSPLIT + split;
    {
        const float* sa = (const float*)sacc4;     // [8][256]
        float v = 0.f;
        #pragma unroll
        for (int w = 0; w < 8; w++) v += sa[w * MM + t];
        g_pacc[idx * MM + t] = v;
    }
    if (t == 0) {
        float bs = 0.f, bc = 0.f;
        #pragma unroll
        for (int i = 0; i < 8; i++) { bs += ssum[i]; bc += scp[i]; }
        g_psum[idx] = bs;
        g_pc[idx]   = bc;
    }

    // ---- handoff: last block of this b merges the 16 partials ----
    __syncthreads();
    __threadfence();                      // release
    if (t == 0) s_old = atomicAdd(&g_cnt[b], 1u);
    __syncthreads();
    if (s_old != NSPLIT - 1) return;
    __threadfence();                      // acquire

    if (t == 0) {
        float Z = 0.f, C = 0.f;
        #pragma unroll
        for (int s = 0; s < NSPLIT; s++) {
            Z += g_psum[b * NSPLIT + s];
            C += g_pc[b * NSPLIT + s];
        }
        red2[0] = 1.f / Z;
        red2[1] = C;
    }
    __syncthreads();
    float invZ = red2[0], C = red2[1];

    float r = 0.f;
    #pragma unroll
    for (int s = 0; s < NSPLIT; s++)
        r += g_pacc[(b * NSPLIT + s) * MM + t];
    out[b * MM + t] = (r + C * kf[b * MM + t]) * invZ;

    if (t == 0) g_cnt[b] = 0u;           // reset for next graph replay
}

// -------------------------------------------------------------------
extern "C" void kernel_launch(void* const* d_in, const int* in_sizes, int n_in,
                              void* d_out, int out_size) {
    const float* memory    = (const float*)d_in[0];   // (B,N,M)
    const float* k         = (const float*)d_in[1];   // (B,M)
    const float* g         = (const float*)d_in[2];   // (B,1)
    // d_in[3] = gamma  -> dead code w.r.t. output
    const float* w_prev    = (const float*)d_in[4];   // (B,2,N)
    const int*   w_lu_prev = (const int*)  d_in[5];   // (B,N)
    // d_in[6] = n      -> dead code w.r.t. output
    float* out = (float*)d_out;                        // (B,M)

    fused_kernel<<<dim3(BB, NSPLIT), 256>>>(
        (const float4*)memory, (const float4*)k, k, g, w_prev, w_lu_prev, out);
}